// round 10
// baseline (speedup 1.0000x reference)
#include <cuda_runtime.h>
#include <cstdint>

// Deformable attention, single level (L=1), 50x50 feature map.
// value (16, 2500, 8, 32) f32 | loc (16,2000,8,1,4,2) f32 | aw (16,2000,8,1,4) f32
// out (16, 2000, 256) f32
//
// One block (1024 thr) per (b,h). The 320KB value slice is staged in smem in
// TWO passes of 25 y-rows (160KB each). All bilinear gathers are LDS from the
// staged slice (128B/cyc crossbar, no L1 gather replays). Corners belong to
// exactly one pass (by clamped y-row); off-pass corners are weight-masked and
// their LDS is PTX-predicated off (no crossbar traffic). Pass 0 writes partial
// sums to out; pass 1 does out += partial.
// Warp = 4 consecutive queries; lane>>3 = query-in-warp, lane&7 = channel quad.

#define FW 50
#define FH 50
#define BS 16
#define QN 2000
#define HN 8
#define DN 32
#define KN (FW * FH)
#define RPP 25                  // y-rows per pass
#define KP (RPP * FW)           // 1250 feature rows per pass
#define SMEM_BYTES (KP * DN * 4)  // 160000 B

__global__ __launch_bounds__(1024, 1)
void deform_attn_kernel(const float4* __restrict__ value4,
                        const float4* __restrict__ loc4,
                        const float4* __restrict__ aw4,
                        float4* __restrict__ out4) {
    extern __shared__ float4 s4[];          // KP rows x 8 float4

    const int bh  = blockIdx.x;             // 0..127
    const int b   = bh >> 3;
    const int h   = bh & (HN - 1);
    const int tid = threadIdx.x;
    const int lane = tid & 31, wib = tid >> 5;
    const int group = lane >> 3, sub = lane & 7;

    // u32 shared base for predicated inline-asm LDS
    unsigned int sbase;
    asm("{ .reg .u64 t; cvta.to.shared.u64 t, %1; cvt.u32.u64 %0, t; }"
        : "=r"(sbase) : "l"(s4));

    // float4 base index of value row k=0 for (b,h)
    const size_t vbase4 = ((size_t)b * KN * HN + h) * 8;

    #pragma unroll
    for (int P = 0; P < 2; P++) {
        const int ybase = P * RPP;

        // ---- stage fill: rows [P*KP, P*KP + KP) ----
        __syncthreads();                     // prior pass consumers done
        for (int i = tid; i < KP * 8; i += 1024) {
            const int k = i >> 3, quad = i & 7;
            s4[i] = __ldg(value4 + vbase4 + (size_t)(P * KP + k) * (HN * 8) + quad);
        }
        __syncthreads();

        // ---- consume: warp handles 4 consecutive queries per iteration ----
        for (int q4 = wib * 4; q4 < QN; q4 += 128) {
            const int t = (b * QN + q4 + group) * HN + h;

            const float4 l01 = __ldg(loc4 + (size_t)t * 2);
            const float4 l23 = __ldg(loc4 + (size_t)t * 2 + 1);
            const float4 a4  = __ldg(aw4 + t);
            const float px[4] = {l01.x, l01.z, l23.x, l23.z};
            const float py[4] = {l01.y, l01.w, l23.y, l23.w};
            const float pa[4] = {a4.x, a4.y, a4.z, a4.w};

            unsigned long long acc01 = 0ull, acc23 = 0ull;

            #pragma unroll
            for (int pp = 0; pp < 2; pp++) {
                unsigned int saddr[2][4];
                float        wgt  [2][4];

                #pragma unroll
                for (int j = 0; j < 2; j++) {
                    const int p = pp * 2 + j;
                    float x = fmaf(px[p], (float)FW, -0.5f);
                    float y = fmaf(py[p], (float)FH, -0.5f);
                    float xf = floorf(x), yf = floorf(y);
                    int x0 = (int)xf, y0 = (int)yf;
                    float fx1 = x - xf, fx0 = 1.0f - fx1;
                    float fy1 = y - yf, fy0 = 1.0f - fy1;
                    float a = pa[p];

                    // x validity one-sided (loc in [0,1])
                    float ax0 = (x0 >= 0)          ? a * fx0 : 0.0f;
                    float ax1 = (x0 + 1 <= FW - 1) ? a * fx1 : 0.0f;
                    int x0c = max(x0, 0), x1c = min(x0 + 1, FW - 1);

                    // y validity AND pass membership of the clamped row
                    int y0c = max(y0, 0);                 // y0 <= 49 always
                    int y1c = min(y0 + 1, FH - 1);        // y1 >= 0 always
                    float by0 = (y0 >= 0 &&
                                 y0c >= ybase && y0c < ybase + RPP) ? fy0 : 0.0f;
                    float by1 = (y0 + 1 <= FH - 1 &&
                                 y1c >= ybase && y1c < ybase + RPP) ? fy1 : 0.0f;

                    // smem-relative rows, clamped safe for the (pred-off) case
                    int r0 = min(max(y0c - ybase, 0), RPP - 1) * FW;
                    int r1 = min(max(y1c - ybase, 0), RPP - 1) * FW;

                    const unsigned int lb = sbase + sub * 16u;
                    saddr[j][0] = lb + (unsigned)(r0 + x0c) * 128u;  wgt[j][0] = ax0 * by0;
                    saddr[j][1] = lb + (unsigned)(r0 + x1c) * 128u;  wgt[j][1] = ax1 * by0;
                    saddr[j][2] = lb + (unsigned)(r1 + x0c) * 128u;  wgt[j][2] = ax0 * by1;
                    saddr[j][3] = lb + (unsigned)(r1 + x1c) * 128u;  wgt[j][3] = ax1 * by1;
                }

                // batch of 8 predicated LDS.128 (off-pass corners: no traffic)
                unsigned long long v0[2][4], v1[2][4];
                #pragma unroll
                for (int j = 0; j < 2; j++)
                    #pragma unroll
                    for (int c = 0; c < 4; c++) {
                        unsigned long long a0 = 0ull, a1 = 0ull;
                        asm volatile(
                            "{ .reg .pred p; setp.ne.f32 p, %2, 0f00000000;\n\t"
                            "  @p ld.shared.v2.u64 {%0, %1}, [%3]; }"
                            : "+l"(a0), "+l"(a1)
                            : "f"(wgt[j][c]), "r"(saddr[j][c]));
                        v0[j][c] = a0; v1[j][c] = a1;
                    }

                #pragma unroll
                for (int j = 0; j < 2; j++)
                    #pragma unroll
                    for (int c = 0; c < 4; c++) {
                        unsigned long long w2;
                        asm("mov.b64 %0, {%1, %1};" : "=l"(w2) : "f"(wgt[j][c]));
                        asm("fma.rn.f32x2 %0, %1, %2, %0;"
                            : "+l"(acc01) : "l"(v0[j][c]), "l"(w2));
                        asm("fma.rn.f32x2 %0, %1, %2, %0;"
                            : "+l"(acc23) : "l"(v1[j][c]), "l"(w2));
                    }
            }

            float4 o;
            asm("mov.b64 {%0, %1}, %2;" : "=f"(o.x), "=f"(o.y) : "l"(acc01));
            asm("mov.b64 {%0, %1}, %2;" : "=f"(o.z), "=f"(o.w) : "l"(acc23));

            const size_t oi = (size_t)t * 8 + sub;
            if (P == 0) {
                out4[oi] = o;                 // first pass: overwrite poison
            } else {
                float4 prev = out4[oi];       // second pass: accumulate
                o.x += prev.x; o.y += prev.y; o.z += prev.z; o.w += prev.w;
                out4[oi] = o;
            }
        }
    }
}

extern "C" void kernel_launch(void* const* d_in, const int* in_sizes, int n_in,
                              void* d_out, int out_size) {
    const float4* value = (const float4*)d_in[0];
    // d_in[1] = value_spatial_shapes (int64), unused (compile-time 50x50)
    const float4* loc = (const float4*)d_in[2];
    const float4* aw  = (const float4*)d_in[3];
    float4* out = (float4*)d_out;

    cudaFuncSetAttribute(deform_attn_kernel,
                         cudaFuncAttributeMaxDynamicSharedMemorySize, SMEM_BYTES);

    deform_attn_kernel<<<BS * HN, 1024, SMEM_BYTES>>>(value, loc, aw, out);
}

// round 11
// speedup vs baseline: 1.9681x; 1.9681x over previous
#include <cuda_runtime.h>
#include <cuda_fp16.h>
#include <cstdint>

// Deformable attention, single level (L=1), 50x50 feature map.
// value (16, 2500, 8, 32) f32 | loc (16,2000,8,1,4,2) f32 | aw (16,2000,8,1,4) f32
// out (16, 2000, 256) f32
//
// One block (1024 thr) per (b,h). The value slice is converted f32->fp16
// DURING the smem fill: 2500 rows x 32ch x 2B = 160000B -> whole slice fits,
// single pass, no masking. All gathers are LDS.128: warp = 8 queries
// (lane>>2 = query, lane&3 = 16B chunk = 8 fp16 channels); one LDS serves a
// full bilinear corner for 8 queries. Weights/accumulation stay f32
// (rel-err budget 1e-3, fp16 value contributes ~2e-4).

#define FW 50
#define FH 50
#define BS 16
#define QN 2000
#define HN 8
#define DN 32
#define KN (FW * FH)
#define SMEM_BYTES (KN * DN * 2)   // 160000

__global__ __launch_bounds__(1024, 1)
void deform_attn_kernel(const float4* __restrict__ value4,
                        const float4* __restrict__ loc4,
                        const float4* __restrict__ aw4,
                        float4* __restrict__ out4) {
    extern __shared__ char sraw[];
    uint2* s2 = reinterpret_cast<uint2*>(sraw);          // row k = 8 uint2 (32 fp16)
    const uint4* srow = reinterpret_cast<const uint4*>(sraw); // row k = 4 uint4

    const int bh  = blockIdx.x;          // 0..127
    const int b   = bh >> 3;
    const int h   = bh & (HN - 1);
    const int tid = threadIdx.x;
    const int lane = tid & 31, wib = tid >> 5;
    const int g   = lane >> 2;           // query within warp (0..7)
    const int sub = lane & 3;            // 16B chunk = channels [sub*8, sub*8+8)

    // ---- fill: f32 -> fp16 convert into smem ----
    const size_t vbase4 = ((size_t)b * KN * HN + h) * (DN / 4);
    for (int i = tid; i < KN * 8; i += 1024) {
        const int k = i >> 3, quad = i & 7;
        float4 v = __ldg(value4 + vbase4 + (size_t)k * (HN * DN / 4) + quad);
        __half2 h01 = __floats2half2_rn(v.x, v.y);
        __half2 h23 = __floats2half2_rn(v.z, v.w);
        uint2 u;
        u.x = *reinterpret_cast<unsigned*>(&h01);
        u.y = *reinterpret_cast<unsigned*>(&h23);
        s2[i] = u;
    }
    __syncthreads();

    // ---- consume: warp = 8 consecutive queries per iteration ----
    // QN=2000 divisible by 8 -> no per-lane guards; warps with q0>=QN skip.
    for (int q0 = wib * 8; q0 < QN; q0 += 32 * 8) {
        const int q = q0 + g;
        const int t = (b * QN + q) * HN + h;

        const float4 l01 = __ldg(loc4 + (size_t)t * 2);
        const float4 l23 = __ldg(loc4 + (size_t)t * 2 + 1);
        const float4 a4  = __ldg(aw4 + t);
        const float px[4] = {l01.x, l01.z, l23.x, l23.z};
        const float py[4] = {l01.y, l01.w, l23.y, l23.w};
        const float pa[4] = {a4.x, a4.y, a4.z, a4.w};

        float acc[8];
        #pragma unroll
        for (int i = 0; i < 8; i++) acc[i] = 0.0f;

        #pragma unroll
        for (int p = 0; p < 4; p++) {
            float x = fmaf(px[p], (float)FW, -0.5f);
            float y = fmaf(py[p], (float)FH, -0.5f);
            float xf = floorf(x), yf = floorf(y);
            int x0 = (int)xf, y0 = (int)yf;
            float fx1 = x - xf, fx0 = 1.0f - fx1;
            float fy1 = y - yf, fy0 = 1.0f - fy1;
            float a = pa[p];

            // one-sided validity (loc in [0,1] -> x0,y0 >= -1; x1,y1 <= 50)
            float ax0 = (x0 >= 0)          ? a * fx0 : 0.0f;
            float ax1 = (x0 + 1 <= FW - 1) ? a * fx1 : 0.0f;
            float by0 = (y0 >= 0)          ? fy0 : 0.0f;
            float by1 = (y0 + 1 <= FH - 1) ? fy1 : 0.0f;
            int x0c = max(x0, 0), x1c = min(x0 + 1, FW - 1);
            int y0c = max(y0, 0), y1c = min(y0 + 1, FH - 1);
            int r0 = y0c * FW, r1 = y1c * FW;

            const int   kidx[4] = {r0 + x0c, r0 + x1c, r1 + x0c, r1 + x1c};
            const float wgt [4] = {ax0 * by0, ax1 * by0, ax0 * by1, ax1 * by1};

            // 4 LDS.128: each serves this corner for all 8 queries in the warp
            uint4 r[4];
            #pragma unroll
            for (int c = 0; c < 4; c++)
                r[c] = srow[kidx[c] * 4 + sub];

            #pragma unroll
            for (int c = 0; c < 4; c++) {
                const float w = wgt[c];
                float2 f0 = __half22float2(*reinterpret_cast<__half2*>(&r[c].x));
                float2 f1 = __half22float2(*reinterpret_cast<__half2*>(&r[c].y));
                float2 f2 = __half22float2(*reinterpret_cast<__half2*>(&r[c].z));
                float2 f3 = __half22float2(*reinterpret_cast<__half2*>(&r[c].w));
                acc[0] = fmaf(w, f0.x, acc[0]);
                acc[1] = fmaf(w, f0.y, acc[1]);
                acc[2] = fmaf(w, f1.x, acc[2]);
                acc[3] = fmaf(w, f1.y, acc[3]);
                acc[4] = fmaf(w, f2.x, acc[4]);
                acc[5] = fmaf(w, f2.y, acc[5]);
                acc[6] = fmaf(w, f3.x, acc[6]);
                acc[7] = fmaf(w, f3.y, acc[7]);
            }
        }

        // out channels [sub*8, sub*8+8): two float4 stores, 128B row per query
        float4 o0 = make_float4(acc[0], acc[1], acc[2], acc[3]);
        float4 o1 = make_float4(acc[4], acc[5], acc[6], acc[7]);
        out4[(size_t)t * 8 + sub * 2]     = o0;
        out4[(size_t)t * 8 + sub * 2 + 1] = o1;
    }
}

extern "C" void kernel_launch(void* const* d_in, const int* in_sizes, int n_in,
                              void* d_out, int out_size) {
    const float4* value = (const float4*)d_in[0];
    // d_in[1] = value_spatial_shapes (int64), unused (compile-time 50x50)
    const float4* loc = (const float4*)d_in[2];
    const float4* aw  = (const float4*)d_in[3];
    float4* out = (float4*)d_out;

    cudaFuncSetAttribute(deform_attn_kernel,
                         cudaFuncAttributeMaxDynamicSharedMemorySize, SMEM_BYTES);

    deform_attn_kernel<<<BS * HN, 1024, SMEM_BYTES>>>(value, loc, aw, out);
}